// round 1
// baseline (speedup 1.0000x reference)
#include <cuda_runtime.h>
#include <cuda_bf16.h>
#include <cstdint>

// Problem constants
#define B_  32
#define T_  512
#define D_  512
#define E_  8
#define H_  2048

// Device-side dispatch table and hidden-activation scratch (alloc-free rule:
// __device__ globals are the sanctioned scratch mechanism).
__device__ int   g_chosen[B_];
__device__ float g_h[(size_t)B_ * T_ * H_];   // 32*512*2048 f32 = 134 MB

// ---------------------------------------------------------------------------
// Router: pooled mean over T, logits = pooled@Wp + bp, softmax, argmax.
// One block per batch, 256 threads.
// ---------------------------------------------------------------------------
__global__ void router_kernel(const float* __restrict__ x,
                              const float* __restrict__ Wp,
                              const float* __restrict__ bp,
                              float* __restrict__ probs_out,   // may be null
                              float* __restrict__ chosen_out)  // may be null
{
    __shared__ float pooled[D_];
    __shared__ float logits[E_];

    const int b = blockIdx.x;
    const float* xb = x + (size_t)b * T_ * D_;

    // pooled[d] = mean over t of x[b,t,d]
    for (int d = threadIdx.x; d < D_; d += blockDim.x) {
        float s = 0.0f;
        #pragma unroll 4
        for (int t = 0; t < T_; ++t) s += xb[(size_t)t * D_ + d];
        pooled[d] = s * (1.0f / (float)T_);
    }
    __syncthreads();

    const int warp = threadIdx.x >> 5;
    const int lane = threadIdx.x & 31;
    if (warp < E_) {
        float s = 0.0f;
        for (int d = lane; d < D_; d += 32) s += pooled[d] * Wp[d * E_ + warp];
        #pragma unroll
        for (int off = 16; off > 0; off >>= 1)
            s += __shfl_down_sync(0xffffffffu, s, off);
        if (lane == 0) logits[warp] = s + bp[warp];
    }
    __syncthreads();

    if (threadIdx.x == 0) {
        float m = logits[0];
        int arg = 0;
        #pragma unroll
        for (int e = 1; e < E_; ++e)
            if (logits[e] > m) { m = logits[e]; arg = e; }   // first-max tie-break
        float ex[E_];
        float sum = 0.0f;
        #pragma unroll
        for (int e = 0; e < E_; ++e) { ex[e] = expf(logits[e] - m); sum += ex[e]; }
        const float inv = 1.0f / sum;
        if (probs_out) {
            #pragma unroll
            for (int e = 0; e < E_; ++e) probs_out[b * E_ + e] = ex[e] * inv;
        }
        if (chosen_out) chosen_out[b] = (float)arg;
        g_chosen[b] = arg;
    }
}

// ---------------------------------------------------------------------------
// Batched expert SGEMM: C[b] = act( A[b] @ W[chosen[b]] + bias[chosen[b]] )
//   A:    [B, M, K]  row-major
//   Wall: [E, K, N]  row-major
//   ball: [E, N]
//   C:    [B, M, N]
// 128x128 tile, BK=8, 256 threads, 8x8 per-thread microtile, fp32 accum.
// M, N, K are multiples of 128 / 4 as used here.
// ---------------------------------------------------------------------------
template <bool RELU>
__global__ __launch_bounds__(256)
void batched_expert_sgemm(const float* __restrict__ A,
                          const float* __restrict__ Wall,
                          const float* __restrict__ ball,
                          float* __restrict__ C,
                          int M, int N, int K)
{
    constexpr int BM = 128, BN = 128, BK = 8, TM = 8, TN = 8;

    __shared__ float As[BK][BM];
    __shared__ float Bs[BK][BN];

    const int b  = blockIdx.z;
    const int e  = g_chosen[b];
    const int bx = blockIdx.x;   // N tile
    const int by = blockIdx.y;   // M tile

    const float* Ab = A    + (size_t)b * M * K + (size_t)(by * BM) * K;
    const float* Wb = Wall + (size_t)e * K * N + (size_t)(bx * BN);

    const int tid = threadIdx.x;

    // A tile loads: 128 rows x 8 k, one float4 per thread
    const int aRow = tid >> 1;            // 0..127
    const int aCol = (tid & 1) * 4;       // 0 or 4
    // B tile loads: 8 k rows x 128 cols, one float4 per thread
    const int bRow = tid >> 5;            // 0..7
    const int bCol = (tid & 31) * 4;      // 0..124

    const int ty = tid >> 4;              // 0..15 -> output rows ty*8..
    const int tx = tid & 15;              // 0..15 -> output cols tx*8..

    float acc[TM][TN];
    #pragma unroll
    for (int i = 0; i < TM; ++i)
        #pragma unroll
        for (int j = 0; j < TN; ++j) acc[i][j] = 0.0f;

    for (int k0 = 0; k0 < K; k0 += BK) {
        float4 av = *reinterpret_cast<const float4*>(Ab + (size_t)aRow * K + k0 + aCol);
        As[aCol + 0][aRow] = av.x;
        As[aCol + 1][aRow] = av.y;
        As[aCol + 2][aRow] = av.z;
        As[aCol + 3][aRow] = av.w;

        float4 bv = *reinterpret_cast<const float4*>(Wb + (size_t)(k0 + bRow) * N + bCol);
        *reinterpret_cast<float4*>(&Bs[bRow][bCol]) = bv;

        __syncthreads();

        #pragma unroll
        for (int kk = 0; kk < BK; ++kk) {
            float ra[TM], rb[TN];
            #pragma unroll
            for (int i = 0; i < TM; ++i) ra[i] = As[kk][ty * TM + i];
            #pragma unroll
            for (int j = 0; j < TN; ++j) rb[j] = Bs[kk][tx * TN + j];
            #pragma unroll
            for (int i = 0; i < TM; ++i)
                #pragma unroll
                for (int j = 0; j < TN; ++j)
                    acc[i][j] = fmaf(ra[i], rb[j], acc[i][j]);
        }
        __syncthreads();
    }

    const float* bias = ball + (size_t)e * N + (size_t)(bx * BN);
    float* Cb = C + (size_t)b * M * N + (size_t)(by * BM) * N + (size_t)(bx * BN);

    #pragma unroll
    for (int i = 0; i < TM; ++i) {
        const int row = ty * TM + i;
        #pragma unroll
        for (int j = 0; j < TN; j += 4) {
            const int col = tx * TN + j;
            float4 v;
            v.x = acc[i][j + 0] + bias[col + 0];
            v.y = acc[i][j + 1] + bias[col + 1];
            v.z = acc[i][j + 2] + bias[col + 2];
            v.w = acc[i][j + 3] + bias[col + 3];
            if (RELU) {
                v.x = fmaxf(v.x, 0.0f);
                v.y = fmaxf(v.y, 0.0f);
                v.z = fmaxf(v.z, 0.0f);
                v.w = fmaxf(v.w, 0.0f);
            }
            *reinterpret_cast<float4*>(&Cb[(size_t)row * N + col]) = v;
        }
    }
}

// ---------------------------------------------------------------------------
// kernel_launch
// Inputs (metadata order): x[B,T,D], Wp[D,E], bp[E], W1[E,D,H], b1[E,H],
//                          W2[E,H,D], b2[E,D]
// Output: concat(final[B,T,D], probs[B,E], expert_chosen[B,1]) as f32.
// ---------------------------------------------------------------------------
extern "C" void kernel_launch(void* const* d_in, const int* in_sizes, int n_in,
                              void* d_out, int out_size)
{
    const float* x  = (const float*)d_in[0];
    const float* Wp = (const float*)d_in[1];
    const float* bp = (const float*)d_in[2];
    const float* W1 = (const float*)d_in[3];
    const float* b1 = (const float*)d_in[4];
    const float* W2 = (const float*)d_in[5];
    const float* b2 = (const float*)d_in[6];

    float* out = (float*)d_out;

    const long long FINAL_N = (long long)B_ * T_ * D_;      // 8,388,608
    float* probs_out  = nullptr;
    float* chosen_out = nullptr;
    if ((long long)out_size >= FINAL_N + (long long)B_ * E_)
        probs_out = out + FINAL_N;
    if ((long long)out_size >= FINAL_N + (long long)B_ * E_ + B_)
        chosen_out = out + FINAL_N + (long long)B_ * E_;

    float* h_scratch;
    cudaGetSymbolAddress((void**)&h_scratch, g_h);

    // 1) Router: chooses expert per batch, writes probs + chosen.
    router_kernel<<<B_, 256>>>(x, Wp, bp, probs_out, chosen_out);

    // 2) h = relu(x @ W1[e] + b1[e])   : M=T, N=H, K=D
    {
        dim3 grid(H_ / 128, T_ / 128, B_);   // (16, 4, 32)
        batched_expert_sgemm<true><<<grid, 256>>>(x, W1, b1, h_scratch,
                                                  T_, H_, D_);
    }

    // 3) final = h @ W2[e] + b2[e]     : M=T, N=D, K=H
    {
        dim3 grid(D_ / 128, T_ / 128, B_);   // (4, 4, 32)
        batched_expert_sgemm<false><<<grid, 256>>>(h_scratch, W2, b2, out,
                                                   T_, D_, H_);
    }
}

// round 3
// speedup vs baseline: 3.1216x; 3.1216x over previous
#include <cuda_runtime.h>
#include <cuda_bf16.h>
#include <cstdint>

#define B_  32
#define T_  512
#define D_  512
#define E_  8
#define H_  2048

// ---------------------------------------------------------------------------
// Device scratch (__device__ globals: the sanctioned no-alloc scratch)
// ---------------------------------------------------------------------------
__device__ int   g_chosen[B_];
__device__ float g_pool_part[B_ * 32 * D_];                 // 2 MB
__device__ __nv_bfloat16 g_x_hi[(size_t)B_ * T_ * D_];      // 16 MB
__device__ __nv_bfloat16 g_x_lo[(size_t)B_ * T_ * D_];
__device__ __nv_bfloat16 g_h_hi[(size_t)B_ * T_ * H_];      // 64 MB
__device__ __nv_bfloat16 g_h_lo[(size_t)B_ * T_ * H_];
__device__ __nv_bfloat16 g_W1T_hi[(size_t)E_ * D_ * H_];    // 16 MB  [E][H][D]
__device__ __nv_bfloat16 g_W1T_lo[(size_t)E_ * D_ * H_];
__device__ __nv_bfloat16 g_W2T_hi[(size_t)E_ * H_ * D_];    // [E][D][H]
__device__ __nv_bfloat16 g_W2T_lo[(size_t)E_ * H_ * D_];

// ---------------------------------------------------------------------------
// PTX helpers (sm_80-baseline only: cp.async, ldmatrix, mma.sync)
// ---------------------------------------------------------------------------
__device__ __forceinline__ uint32_t smem_to_u32(const void* p) {
    uint32_t a;
    asm("{ .reg .u64 t; cvta.to.shared.u64 t, %1; cvt.u32.u64 %0, t; }"
        : "=r"(a) : "l"(p));
    return a;
}

__device__ __forceinline__ void cp16(uint32_t dst, const void* src) {
    asm volatile("cp.async.cg.shared.global [%0], [%1], 16;"
                 :: "r"(dst), "l"(src));
}
#define CP_COMMIT() asm volatile("cp.async.commit_group;" ::: "memory")
#define CP_WAIT1()  asm volatile("cp.async.wait_group 1;"  ::: "memory")

__device__ __forceinline__ void ldsm4(uint32_t* d, uint32_t addr) {
    asm volatile("ldmatrix.sync.aligned.m8n8.x4.shared.b16 {%0,%1,%2,%3}, [%4];"
                 : "=r"(d[0]), "=r"(d[1]), "=r"(d[2]), "=r"(d[3])
                 : "r"(addr));
}

__device__ __forceinline__ void mma16816(float* c, const uint32_t* a,
                                         const uint32_t* b) {
    asm volatile(
        "mma.sync.aligned.m16n8k16.row.col.f32.bf16.bf16.f32 "
        "{%0,%1,%2,%3}, {%4,%5,%6,%7}, {%8,%9}, {%0,%1,%2,%3};"
        : "+f"(c[0]), "+f"(c[1]), "+f"(c[2]), "+f"(c[3])
        : "r"(a[0]), "r"(a[1]), "r"(a[2]), "r"(a[3]),
          "r"(b[0]), "r"(b[1]));
}

// ---------------------------------------------------------------------------
// Kernel 1: convert x -> bf16 hi/lo, emit partial pooled sums
// ---------------------------------------------------------------------------
__global__ __launch_bounds__(256)
void xconv_pool_kernel(const float* __restrict__ x,
                       __nv_bfloat16* __restrict__ xhi,
                       __nv_bfloat16* __restrict__ xlo,
                       float* __restrict__ pool_part)
{
    const int b  = blockIdx.x;
    const int tc = blockIdx.y;
    const int d0 = threadIdx.x * 2;

    float s0 = 0.0f, s1 = 0.0f;
    #pragma unroll 4
    for (int r = 0; r < 16; ++r) {
        const int t = tc * 16 + r;
        const size_t off = ((size_t)b * T_ + t) * D_ + d0;
        const float2 v = *reinterpret_cast<const float2*>(x + off);
        s0 += v.x; s1 += v.y;
        __nv_bfloat16 h0 = __float2bfloat16(v.x);
        __nv_bfloat16 h1 = __float2bfloat16(v.y);
        __nv_bfloat16 l0 = __float2bfloat16(v.x - __bfloat162float(h0));
        __nv_bfloat16 l1 = __float2bfloat16(v.y - __bfloat162float(h1));
        *reinterpret_cast<__nv_bfloat162*>(xhi + off) = __nv_bfloat162(h0, h1);
        *reinterpret_cast<__nv_bfloat162*>(xlo + off) = __nv_bfloat162(l0, l1);
    }
    float2 s = make_float2(s0, s1);
    *reinterpret_cast<float2*>(pool_part + ((size_t)b * 32 + tc) * D_ + d0) = s;
}

// ---------------------------------------------------------------------------
// Kernel 2: weight transpose+convert. src [E][R][C] f32 -> dst [E][C][R] hi/lo
// ---------------------------------------------------------------------------
__global__ __launch_bounds__(256)
void wtrans_kernel(const float* __restrict__ src,
                   __nv_bfloat16* __restrict__ dhi,
                   __nv_bfloat16* __restrict__ dlo,
                   int R, int C)
{
    __shared__ float s[32][33];
    const int e  = blockIdx.z;
    const int c0 = blockIdx.x * 32;
    const int r0 = blockIdx.y * 32;
    const size_t ebase = (size_t)e * R * C;

    #pragma unroll
    for (int k = 0; k < 4; ++k) {
        int idx = threadIdx.x + k * 256;
        int rr = idx >> 5, cc = idx & 31;
        s[rr][cc] = src[ebase + (size_t)(r0 + rr) * C + (c0 + cc)];
    }
    __syncthreads();
    #pragma unroll
    for (int k = 0; k < 4; ++k) {
        int idx = threadIdx.x + k * 256;
        int rr = idx >> 5, cc = idx & 31;
        float v = s[cc][rr];
        __nv_bfloat16 hi = __float2bfloat16(v);
        __nv_bfloat16 lo = __float2bfloat16(v - __bfloat162float(hi));
        size_t off = ebase + (size_t)(c0 + rr) * R + (r0 + cc);
        dhi[off] = hi;
        dlo[off] = lo;
    }
}

// ---------------------------------------------------------------------------
// Kernel 3: router from pooled partials
// ---------------------------------------------------------------------------
__global__ __launch_bounds__(256)
void router_kernel(const float* __restrict__ pool_part,
                   const float* __restrict__ Wp,
                   const float* __restrict__ bp,
                   float* __restrict__ probs_out,
                   float* __restrict__ chosen_out)
{
    __shared__ float pooled[D_];
    __shared__ float logits[E_];
    const int b = blockIdx.x;

    for (int d = threadIdx.x; d < D_; d += 256) {
        float s = 0.0f;
        #pragma unroll
        for (int p = 0; p < 32; ++p)
            s += pool_part[((size_t)b * 32 + p) * D_ + d];
        pooled[d] = s * (1.0f / (float)T_);
    }
    __syncthreads();

    const int warp = threadIdx.x >> 5, lane = threadIdx.x & 31;
    {
        float s = 0.0f;
        for (int d = lane; d < D_; d += 32) s += pooled[d] * Wp[d * E_ + warp];
        #pragma unroll
        for (int off = 16; off > 0; off >>= 1)
            s += __shfl_down_sync(0xffffffffu, s, off);
        if (lane == 0) logits[warp] = s + bp[warp];
    }
    __syncthreads();

    if (threadIdx.x == 0) {
        float m = logits[0]; int arg = 0;
        #pragma unroll
        for (int e = 1; e < E_; ++e)
            if (logits[e] > m) { m = logits[e]; arg = e; }
        float ex[E_], sum = 0.0f;
        #pragma unroll
        for (int e = 0; e < E_; ++e) { ex[e] = expf(logits[e] - m); sum += ex[e]; }
        const float inv = 1.0f / sum;
        if (probs_out) {
            #pragma unroll
            for (int e = 0; e < E_; ++e) probs_out[b * E_ + e] = ex[e] * inv;
        }
        if (chosen_out) chosen_out[b] = (float)arg;
        g_chosen[b] = arg;
    }
}

// ---------------------------------------------------------------------------
// Kernel 4: batched expert GEMM, mma.sync bf16 with hi/lo 3-pass compensation.
//   C[b] = act( A[b] @ BT[e]^T + bias[e] )
//   A:  [B][512][K]  bf16 hi/lo (K-major)
//   BT: [E][Nt][K]   bf16 hi/lo (K-major)
// CTA tile 128x128, BK=64, 3-stage cp.async pipeline, 256 threads (8 warps),
// warp tile 64x32, m16n8k16.
// Stage layout (64KB): Ahi 16K | Alo 16K | Bhi 16K | Blo 16K, rows 128B,
// 16B-quad XOR swizzle (j ^ (row&7)).
// ---------------------------------------------------------------------------
#define STAGE_BYTES 65536
#define GEMM_SMEM   (3 * STAGE_BYTES)

template <bool G1>   // true: relu + bf16 hi/lo out; false: f32 out
__global__ __launch_bounds__(256, 1)
void moe_gemm_kernel(const __nv_bfloat16* __restrict__ Ahi,
                     const __nv_bfloat16* __restrict__ Alo,
                     const __nv_bfloat16* __restrict__ Bhi,
                     const __nv_bfloat16* __restrict__ Blo,
                     const float* __restrict__ biasAll,
                     float* __restrict__ outF,
                     __nv_bfloat16* __restrict__ outHi,
                     __nv_bfloat16* __restrict__ outLo,
                     int K, int Nt)
{
    extern __shared__ char smem[];
    const uint32_t sbase = smem_to_u32(smem);
    const int tid  = threadIdx.x;
    const int lane = tid & 31;
    const int wid  = tid >> 5;
    const int warp_m = wid & 1;          // 2 warps along M (64 each)
    const int warp_n = wid >> 1;         // 4 warps along N (32 each)

    const int b  = blockIdx.z;
    const int e  = g_chosen[b];
    const int m0 = blockIdx.y * 128;
    const int n0 = blockIdx.x * 128;

    const __nv_bfloat16* Ah = Ahi + (size_t)b * T_ * K + (size_t)m0 * K;
    const __nv_bfloat16* Al = Alo + (size_t)b * T_ * K + (size_t)m0 * K;
    const __nv_bfloat16* Bh = Bhi + (size_t)e * Nt * K + (size_t)n0 * K;
    const __nv_bfloat16* Bl = Blo + (size_t)e * Nt * K + (size_t)n0 * K;

    // loader constants: thread t covers quads q = tid + i*256 (i<4) per array
    // row = q>>3 (0..127), j = q&7; smem off = row*128 + (j*16 ^ ((row&7)<<4))
    // ldmatrix constants
    const int ltile = lane >> 3;
    const int lr    = lane & 7;
    const uint32_t xr = (uint32_t)lr << 4;
    const uint32_t baseA = (uint32_t)(warp_m * 64 + (ltile & 1) * 8 + lr) * 128u;
    const uint32_t kcA   = (uint32_t)(ltile >> 1) * 16u;
    const uint32_t baseB = (uint32_t)(warp_n * 32 + (ltile >> 1) * 8 + lr) * 128u;
    const uint32_t kcB   = (uint32_t)(ltile & 1) * 16u;

    float acc[4][4][4];
    #pragma unroll
    for (int mi = 0; mi < 4; ++mi)
        #pragma unroll
        for (int ni = 0; ni < 4; ++ni)
            #pragma unroll
            for (int i = 0; i < 4; ++i) acc[mi][ni][i] = 0.0f;

    const int KB = K >> 6;

    // ---- stage loader ----
    auto load_stage = [&](int stage_idx, int k0) {
        const uint32_t stg = sbase + (uint32_t)stage_idx * STAGE_BYTES;
        #pragma unroll
        for (int i = 0; i < 4; ++i) {
            const int q = tid + i * 256;
            const int row = q >> 3, j = q & 7;
            const uint32_t soff = (uint32_t)row * 128u +
                                  (((uint32_t)j * 16u) ^ (((uint32_t)(row & 7)) << 4));
            const size_t goff = (size_t)row * K + k0 + j * 8;
            cp16(stg + 0u     + soff, Ah + goff);
            cp16(stg + 16384u + soff, Al + goff);
            cp16(stg + 32768u + soff, Bh + goff);
            cp16(stg + 49152u + soff, Bl + goff);
        }
        CP_COMMIT();
    };

    load_stage(0, 0);
    if (KB > 1) load_stage(1, 64);
    else CP_COMMIT();   // keep group count consistent for wait_group 1

    for (int kb = 0; kb < KB; ++kb) {
        CP_WAIT1();
        __syncthreads();
        if (kb + 2 < KB) load_stage((kb + 2) % 3, (kb + 2) << 6);

        const uint32_t stg = sbase + (uint32_t)(kb % 3) * STAGE_BYTES;
        const uint32_t sAh = stg, sAl = stg + 16384u;
        const uint32_t sBh = stg + 32768u, sBl = stg + 49152u;

        #pragma unroll
        for (int kk = 0; kk < 4; ++kk) {
            const uint32_t kA = ((uint32_t)(kk * 32) + kcA) ^ xr;
            const uint32_t kB = ((uint32_t)(kk * 32) + kcB) ^ xr;

            uint32_t ahf[4][4], alf[4][4], bhf[4][2], blf[4][2];
            #pragma unroll
            for (int mi = 0; mi < 4; ++mi) {
                ldsm4(ahf[mi], sAh + baseA + mi * 2048u + kA);
                ldsm4(alf[mi], sAl + baseA + mi * 2048u + kA);
            }
            #pragma unroll
            for (int pi = 0; pi < 2; ++pi) {
                uint32_t t4[4];
                ldsm4(t4, sBh + baseB + pi * 2048u + kB);
                bhf[2*pi][0] = t4[0]; bhf[2*pi][1] = t4[1];
                bhf[2*pi+1][0] = t4[2]; bhf[2*pi+1][1] = t4[3];
                ldsm4(t4, sBl + baseB + pi * 2048u + kB);
                blf[2*pi][0] = t4[0]; blf[2*pi][1] = t4[1];
                blf[2*pi+1][0] = t4[2]; blf[2*pi+1][1] = t4[3];
            }
            #pragma unroll
            for (int mi = 0; mi < 4; ++mi)
                #pragma unroll
                for (int ni = 0; ni < 4; ++ni) {
                    mma16816(acc[mi][ni], ahf[mi], bhf[ni]);
                    mma16816(acc[mi][ni], ahf[mi], blf[ni]);
                    mma16816(acc[mi][ni], alf[mi], bhf[ni]);
                }
        }
    }

    // ---- epilogue ----
    const int gm = m0 + warp_m * 64;
    const int gncol = n0 + warp_n * 32;
    #pragma unroll
    for (int mi = 0; mi < 4; ++mi) {
        const int row0 = gm + mi * 16 + (lane >> 2);
        #pragma unroll
        for (int ni = 0; ni < 4; ++ni) {
            const int col = gncol + ni * 8 + (lane & 3) * 2;
            const float2 bv = *reinterpret_cast<const float2*>(
                biasAll + (size_t)e * Nt + col);
            float v00 = acc[mi][ni][0] + bv.x;
            float v01 = acc[mi][ni][1] + bv.y;
            float v10 = acc[mi][ni][2] + bv.x;
            float v11 = acc[mi][ni][3] + bv.y;
            if (G1) {
                v00 = fmaxf(v00, 0.0f); v01 = fmaxf(v01, 0.0f);
                v10 = fmaxf(v10, 0.0f); v11 = fmaxf(v11, 0.0f);
                const size_t o0 = ((size_t)b * T_ + row0) * Nt + col;
                const size_t o1 = ((size_t)b * T_ + row0 + 8) * Nt + col;
                __nv_bfloat16 h00 = __float2bfloat16(v00);
                __nv_bfloat16 h01 = __float2bfloat16(v01);
                __nv_bfloat16 h10 = __float2bfloat16(v10);
                __nv_bfloat16 h11 = __float2bfloat16(v11);
                *reinterpret_cast<__nv_bfloat162*>(outHi + o0) = __nv_bfloat162(h00, h01);
                *reinterpret_cast<__nv_bfloat162*>(outHi + o1) = __nv_bfloat162(h10, h11);
                *reinterpret_cast<__nv_bfloat162*>(outLo + o0) = __nv_bfloat162(
                    __float2bfloat16(v00 - __bfloat162float(h00)),
                    __float2bfloat16(v01 - __bfloat162float(h01)));
                *reinterpret_cast<__nv_bfloat162*>(outLo + o1) = __nv_bfloat162(
                    __float2bfloat16(v10 - __bfloat162float(h10)),
                    __float2bfloat16(v11 - __bfloat162float(h11)));
            } else {
                const size_t o0 = ((size_t)b * T_ + row0) * Nt + col;
                const size_t o1 = ((size_t)b * T_ + row0 + 8) * Nt + col;
                *reinterpret_cast<float2*>(outF + o0) = make_float2(v00, v01);
                *reinterpret_cast<float2*>(outF + o1) = make_float2(v10, v11);
            }
        }
    }
}

// ---------------------------------------------------------------------------
// kernel_launch
// ---------------------------------------------------------------------------
extern "C" void kernel_launch(void* const* d_in, const int* in_sizes, int n_in,
                              void* d_out, int out_size)
{
    const float* x  = (const float*)d_in[0];
    const float* Wp = (const float*)d_in[1];
    const float* bp = (const float*)d_in[2];
    const float* W1 = (const float*)d_in[3];
    const float* b1 = (const float*)d_in[4];
    const float* W2 = (const float*)d_in[5];
    const float* b2 = (const float*)d_in[6];
    float* out = (float*)d_out;

    const long long FINAL_N = (long long)B_ * T_ * D_;
    float* probs_out  = nullptr;
    float* chosen_out = nullptr;
    if ((long long)out_size >= FINAL_N + (long long)B_ * E_)
        probs_out = out + FINAL_N;
    if ((long long)out_size >= FINAL_N + (long long)B_ * E_ + B_)
        chosen_out = out + FINAL_N + (long long)B_ * E_;

    __nv_bfloat16 *xhi, *xlo, *hhi, *hlo, *w1thi, *w1tlo, *w2thi, *w2tlo;
    float* pool_part;
    cudaGetSymbolAddress((void**)&xhi, g_x_hi);
    cudaGetSymbolAddress((void**)&xlo, g_x_lo);
    cudaGetSymbolAddress((void**)&hhi, g_h_hi);
    cudaGetSymbolAddress((void**)&hlo, g_h_lo);
    cudaGetSymbolAddress((void**)&w1thi, g_W1T_hi);
    cudaGetSymbolAddress((void**)&w1tlo, g_W1T_lo);
    cudaGetSymbolAddress((void**)&w2thi, g_W2T_hi);
    cudaGetSymbolAddress((void**)&w2tlo, g_W2T_lo);
    cudaGetSymbolAddress((void**)&pool_part, g_pool_part);

    cudaFuncSetAttribute(moe_gemm_kernel<true>,
                         cudaFuncAttributeMaxDynamicSharedMemorySize, GEMM_SMEM);
    cudaFuncSetAttribute(moe_gemm_kernel<false>,
                         cudaFuncAttributeMaxDynamicSharedMemorySize, GEMM_SMEM);

    // 1) x -> bf16 hi/lo + pooled partials
    xconv_pool_kernel<<<dim3(B_, 32), 256>>>(x, xhi, xlo, pool_part);

    // 2) weight transpose+convert
    wtrans_kernel<<<dim3(H_ / 32, D_ / 32, E_), 256>>>(W1, w1thi, w1tlo, D_, H_);
    wtrans_kernel<<<dim3(D_ / 32, H_ / 32, E_), 256>>>(W2, w2thi, w2tlo, H_, D_);

    // 3) router
    router_kernel<<<B_, 256>>>(pool_part, Wp, bp, probs_out, chosen_out);

    // 4) h = relu(x @ W1[e] + b1[e])  : M=512, N=2048, K=512
    moe_gemm_kernel<true><<<dim3(H_ / 128, T_ / 128, B_), 256, GEMM_SMEM>>>(
        xhi, xlo, w1thi, w1tlo, b1, nullptr, hhi, hlo, D_, H_);

    // 5) final = h @ W2[e] + b2[e]    : M=512, N=512, K=2048
    moe_gemm_kernel<false><<<dim3(D_ / 128, T_ / 128, B_), 256, GEMM_SMEM>>>(
        hhi, hlo, w2thi, w2tlo, b2, out, nullptr, nullptr, H_, D_);
}

// round 4
// speedup vs baseline: 7.1544x; 2.2919x over previous
#include <cuda_runtime.h>
#include <cuda_fp16.h>
#include <cstdint>

#define B_  32
#define T_  512
#define D_  512
#define E_  8
#define H_  2048

// ---------------------------------------------------------------------------
// Device scratch (__device__ globals: the sanctioned no-alloc scratch)
// ---------------------------------------------------------------------------
__device__ int    g_chosen[B_];
__device__ float  g_pool_part[B_ * 32 * D_];              // 2 MB
__device__ __half g_x_h[(size_t)B_ * T_ * D_];            // 16 MB
__device__ __half g_h_h[(size_t)B_ * T_ * H_];            // 64 MB
__device__ __half g_W1T[(size_t)E_ * D_ * H_];            // 16 MB  [E][H][D]
__device__ __half g_W2T[(size_t)E_ * H_ * D_];            // 16 MB  [E][D][H]

// ---------------------------------------------------------------------------
// PTX helpers (sm_80-baseline only: cp.async, ldmatrix, mma.sync)
// ---------------------------------------------------------------------------
__device__ __forceinline__ uint32_t smem_to_u32(const void* p) {
    uint32_t a;
    asm("{ .reg .u64 t; cvta.to.shared.u64 t, %1; cvt.u32.u64 %0, t; }"
        : "=r"(a) : "l"(p));
    return a;
}

__device__ __forceinline__ void cp16(uint32_t dst, const void* src) {
    asm volatile("cp.async.cg.shared.global [%0], [%1], 16;"
                 :: "r"(dst), "l"(src));
}
#define CP_COMMIT() asm volatile("cp.async.commit_group;" ::: "memory")
#define CP_WAIT1()  asm volatile("cp.async.wait_group 1;"  ::: "memory")

__device__ __forceinline__ void ldsm4(uint32_t* d, uint32_t addr) {
    asm volatile("ldmatrix.sync.aligned.m8n8.x4.shared.b16 {%0,%1,%2,%3}, [%4];"
                 : "=r"(d[0]), "=r"(d[1]), "=r"(d[2]), "=r"(d[3])
                 : "r"(addr));
}

__device__ __forceinline__ void mma16816(float* c, const uint32_t* a,
                                         const uint32_t* b) {
    asm volatile(
        "mma.sync.aligned.m16n8k16.row.col.f32.f16.f16.f32 "
        "{%0,%1,%2,%3}, {%4,%5,%6,%7}, {%8,%9}, {%0,%1,%2,%3};"
        : "+f"(c[0]), "+f"(c[1]), "+f"(c[2]), "+f"(c[3])
        : "r"(a[0]), "r"(a[1]), "r"(a[2]), "r"(a[3]),
          "r"(b[0]), "r"(b[1]));
}

// ---------------------------------------------------------------------------
// Kernel 1: convert x -> fp16, emit partial pooled sums
// grid (B, 32), 256 threads; each thread owns 2 d-columns over 16 t rows
// ---------------------------------------------------------------------------
__global__ __launch_bounds__(256)
void xconv_pool_kernel(const float* __restrict__ x,
                       __half* __restrict__ xh,
                       float* __restrict__ pool_part)
{
    const int b  = blockIdx.x;
    const int tc = blockIdx.y;
    const int d0 = threadIdx.x * 2;

    float s0 = 0.0f, s1 = 0.0f;
    #pragma unroll 4
    for (int r = 0; r < 16; ++r) {
        const int t = tc * 16 + r;
        const size_t off = ((size_t)b * T_ + t) * D_ + d0;
        const float2 v = *reinterpret_cast<const float2*>(x + off);
        s0 += v.x; s1 += v.y;
        *reinterpret_cast<__half2*>(xh + off) =
            __halves2half2(__float2half_rn(v.x), __float2half_rn(v.y));
    }
    *reinterpret_cast<float2*>(pool_part + ((size_t)b * 32 + tc) * D_ + d0) =
        make_float2(s0, s1);
}

// ---------------------------------------------------------------------------
// Kernel 2: weight transpose+convert, both W1 and W2 in one launch.
// W1 [E][D][H] f32 -> [E][H][D] fp16 ;  W2 [E][H][D] f32 -> [E][D][H] fp16
// grid: (C/32, R/32, E*2) where z>>3 selects tensor, z&7 selects expert.
// For W1: R=D, C=H; W2: R=H, C=D. We launch with the max dims and guard.
// Simpler: launch grid (64, 64, 16); W1 uses x<H/32,y<D/32; W2 x<D/32,y<H/32.
// ---------------------------------------------------------------------------
__global__ __launch_bounds__(256)
void wtrans_kernel(const float* __restrict__ W1,
                   const float* __restrict__ W2,
                   __half* __restrict__ W1T,
                   __half* __restrict__ W2T)
{
    __shared__ float s[32][33];
    const int which = blockIdx.z >> 3;          // 0: W1, 1: W2
    const int e     = blockIdx.z & 7;
    const int R = which ? H_ : D_;
    const int C = which ? D_ : H_;
    const int c0 = blockIdx.x * 32;
    const int r0 = blockIdx.y * 32;
    if (c0 >= C || r0 >= R) return;

    const float* src = (which ? W2 : W1) + (size_t)e * R * C;
    __half*      dst = (which ? W2T : W1T) + (size_t)e * R * C;

    #pragma unroll
    for (int k = 0; k < 4; ++k) {
        int idx = threadIdx.x + k * 256;
        int rr = idx >> 5, cc = idx & 31;
        s[rr][cc] = src[(size_t)(r0 + rr) * C + (c0 + cc)];
    }
    __syncthreads();
    #pragma unroll
    for (int k = 0; k < 4; ++k) {
        int idx = threadIdx.x + k * 256;
        int rr = idx >> 5, cc = idx & 31;
        dst[(size_t)(c0 + rr) * R + (r0 + cc)] = __float2half_rn(s[cc][rr]);
    }
}

// ---------------------------------------------------------------------------
// Kernel 3: router from pooled partials
// ---------------------------------------------------------------------------
__global__ __launch_bounds__(256)
void router_kernel(const float* __restrict__ pool_part,
                   const float* __restrict__ Wp,
                   const float* __restrict__ bp,
                   float* __restrict__ probs_out,
                   float* __restrict__ chosen_out)
{
    __shared__ float pooled[D_];
    __shared__ float logits[E_];
    const int b = blockIdx.x;

    for (int d = threadIdx.x; d < D_; d += 256) {
        float s = 0.0f;
        #pragma unroll
        for (int p = 0; p < 32; ++p)
            s += pool_part[((size_t)b * 32 + p) * D_ + d];
        pooled[d] = s * (1.0f / (float)T_);
    }
    __syncthreads();

    const int warp = threadIdx.x >> 5, lane = threadIdx.x & 31;
    {
        float s = 0.0f;
        for (int d = lane; d < D_; d += 32) s += pooled[d] * Wp[d * E_ + warp];
        #pragma unroll
        for (int off = 16; off > 0; off >>= 1)
            s += __shfl_down_sync(0xffffffffu, s, off);
        if (lane == 0) logits[warp] = s + bp[warp];
    }
    __syncthreads();

    if (threadIdx.x == 0) {
        float m = logits[0]; int arg = 0;
        #pragma unroll
        for (int e = 1; e < E_; ++e)
            if (logits[e] > m) { m = logits[e]; arg = e; }
        float ex[E_], sum = 0.0f;
        #pragma unroll
        for (int e = 0; e < E_; ++e) { ex[e] = expf(logits[e] - m); sum += ex[e]; }
        const float inv = 1.0f / sum;
        if (probs_out) {
            #pragma unroll
            for (int e = 0; e < E_; ++e) probs_out[b * E_ + e] = ex[e] * inv;
        }
        if (chosen_out) chosen_out[b] = (float)arg;
        g_chosen[b] = arg;
    }
}

// ---------------------------------------------------------------------------
// Kernel 4: batched expert GEMM, single-pass fp16 mma.sync.
//   C[b] = act( A[b] @ BT[e]^T + bias[e] )
//   A:  [B][512][K]  fp16 (K-major)
//   BT: [E][Nt][K]   fp16 (K-major)
// CTA tile 128x128, BK=64, 3-stage cp.async pipeline (32KB/stage), 256 thr,
// 2 CTAs/SM, warp tile 64x32, m16n8k16.
// ---------------------------------------------------------------------------
#define STAGE_BYTES 32768
#define GEMM_SMEM   (3 * STAGE_BYTES)

template <bool G1>   // true: relu + fp16 out; false: f32 out
__global__ __launch_bounds__(256, 2)
void moe_gemm_kernel(const __half* __restrict__ A,
                     const __half* __restrict__ BT,
                     const float* __restrict__ biasAll,
                     float* __restrict__ outF,
                     __half* __restrict__ outH,
                     int K, int Nt)
{
    extern __shared__ char smem[];
    const uint32_t sbase = smem_to_u32(smem);
    const int tid  = threadIdx.x;
    const int lane = tid & 31;
    const int wid  = tid >> 5;
    const int warp_m = wid & 1;          // 2 warps along M (64 each)
    const int warp_n = wid >> 1;         // 4 warps along N (32 each)

    const int b  = blockIdx.z;
    const int e  = g_chosen[b];
    const int m0 = blockIdx.y * 128;
    const int n0 = blockIdx.x * 128;

    const __half* Ag = A  + (size_t)b * T_ * K + (size_t)m0 * K;
    const __half* Bg = BT + (size_t)e * Nt * K + (size_t)n0 * K;

    // ldmatrix addressing constants
    const int ltile = lane >> 3;
    const int lr    = lane & 7;
    const uint32_t xr = (uint32_t)lr << 4;
    const uint32_t baseA = (uint32_t)(warp_m * 64 + (ltile & 1) * 8 + lr) * 128u;
    const uint32_t kcA   = (uint32_t)(ltile >> 1) * 16u;
    const uint32_t baseB = (uint32_t)(warp_n * 32 + (ltile >> 1) * 8 + lr) * 128u;
    const uint32_t kcB   = (uint32_t)(ltile & 1) * 16u;

    float acc[4][4][4];
    #pragma unroll
    for (int mi = 0; mi < 4; ++mi)
        #pragma unroll
        for (int ni = 0; ni < 4; ++ni)
            #pragma unroll
            for (int i = 0; i < 4; ++i) acc[mi][ni][i] = 0.0f;

    const int KB = K >> 6;

    auto load_stage = [&](int stage_idx, int k0) {
        const uint32_t stg = sbase + (uint32_t)stage_idx * STAGE_BYTES;
        #pragma unroll
        for (int i = 0; i < 4; ++i) {
            const int q = tid + i * 256;          // 0..1023
            const int row = q >> 3, j = q & 7;
            const uint32_t soff = (uint32_t)row * 128u +
                                  (((uint32_t)j * 16u) ^ (((uint32_t)(row & 7)) << 4));
            const size_t goff = (size_t)row * K + k0 + j * 8;
            cp16(stg + soff,          Ag + goff);
            cp16(stg + 16384u + soff, Bg + goff);
        }
        CP_COMMIT();
    };

    load_stage(0, 0);
    if (KB > 1) load_stage(1, 64);
    else CP_COMMIT();

    for (int kb = 0; kb < KB; ++kb) {
        CP_WAIT1();
        __syncthreads();
        if (kb + 2 < KB) load_stage((kb + 2) % 3, (kb + 2) << 6);

        const uint32_t stg = sbase + (uint32_t)(kb % 3) * STAGE_BYTES;
        const uint32_t sA = stg, sB = stg + 16384u;

        #pragma unroll
        for (int kk = 0; kk < 4; ++kk) {
            const uint32_t kA = ((uint32_t)(kk * 32) + kcA) ^ xr;
            const uint32_t kB = ((uint32_t)(kk * 32) + kcB) ^ xr;

            uint32_t af[4][4], bf[4][2];
            #pragma unroll
            for (int mi = 0; mi < 4; ++mi)
                ldsm4(af[mi], sA + baseA + mi * 2048u + kA);
            #pragma unroll
            for (int pi = 0; pi < 2; ++pi) {
                uint32_t t4[4];
                ldsm4(t4, sB + baseB + pi * 2048u + kB);
                bf[2*pi][0]   = t4[0]; bf[2*pi][1]   = t4[1];
                bf[2*pi+1][0] = t4[2]; bf[2*pi+1][1] = t4[3];
            }
            #pragma unroll
            for (int mi = 0; mi < 4; ++mi)
                #pragma unroll
                for (int ni = 0; ni < 4; ++ni)
                    mma16816(acc[mi][ni], af[mi], bf[ni]);
        }
        __syncthreads();
    }

    // ---- epilogue ----
    const int gm = m0 + warp_m * 64;
    const int gncol = n0 + warp_n * 32;
    #pragma unroll
    for (int mi = 0; mi < 4; ++mi) {
        const int row0 = gm + mi * 16 + (lane >> 2);
        #pragma unroll
        for (int ni = 0; ni < 4; ++ni) {
            const int col = gncol + ni * 8 + (lane & 3) * 2;
            const float2 bv = *reinterpret_cast<const float2*>(
                biasAll + (size_t)e * Nt + col);
            float v00 = acc[mi][ni][0] + bv.x;
            float v01 = acc[mi][ni][1] + bv.y;
            float v10 = acc[mi][ni][2] + bv.x;
            float v11 = acc[mi][ni][3] + bv.y;
            const size_t o0 = ((size_t)b * T_ + row0) * Nt + col;
            const size_t o1 = ((size_t)b * T_ + row0 + 8) * Nt + col;
            if (G1) {
                v00 = fmaxf(v00, 0.0f); v01 = fmaxf(v01, 0.0f);
                v10 = fmaxf(v10, 0.0f); v11 = fmaxf(v11, 0.0f);
                *reinterpret_cast<__half2*>(outH + o0) =
                    __halves2half2(__float2half_rn(v00), __float2half_rn(v01));
                *reinterpret_cast<__half2*>(outH + o1) =
                    __halves2half2(__float2half_rn(v10), __float2half_rn(v11));
            } else {
                *reinterpret_cast<float2*>(outF + o0) = make_float2(v00, v01);
                *reinterpret_cast<float2*>(outF + o1) = make_float2(v10, v11);
            }
        }
    }
}

// ---------------------------------------------------------------------------
// kernel_launch
// ---------------------------------------------------------------------------
extern "C" void kernel_launch(void* const* d_in, const int* in_sizes, int n_in,
                              void* d_out, int out_size)
{
    const float* x  = (const float*)d_in[0];
    const float* Wp = (const float*)d_in[1];
    const float* bp = (const float*)d_in[2];
    const float* W1 = (const float*)d_in[3];
    const float* b1 = (const float*)d_in[4];
    const float* W2 = (const float*)d_in[5];
    const float* b2 = (const float*)d_in[6];
    float* out = (float*)d_out;

    const long long FINAL_N = (long long)B_ * T_ * D_;
    float* probs_out  = nullptr;
    float* chosen_out = nullptr;
    if ((long long)out_size >= FINAL_N + (long long)B_ * E_)
        probs_out = out + FINAL_N;
    if ((long long)out_size >= FINAL_N + (long long)B_ * E_ + B_)
        chosen_out = out + FINAL_N + (long long)B_ * E_;

    __half *xh, *hh, *w1t, *w2t;
    float* pool_part;
    cudaGetSymbolAddress((void**)&xh, g_x_h);
    cudaGetSymbolAddress((void**)&hh, g_h_h);
    cudaGetSymbolAddress((void**)&w1t, g_W1T);
    cudaGetSymbolAddress((void**)&w2t, g_W2T);
    cudaGetSymbolAddress((void**)&pool_part, g_pool_part);

    cudaFuncSetAttribute(moe_gemm_kernel<true>,
                         cudaFuncAttributeMaxDynamicSharedMemorySize, GEMM_SMEM);
    cudaFuncSetAttribute(moe_gemm_kernel<false>,
                         cudaFuncAttributeMaxDynamicSharedMemorySize, GEMM_SMEM);

    // 1) x -> fp16 + pooled partials
    xconv_pool_kernel<<<dim3(B_, 32), 256>>>(x, xh, pool_part);

    // 2) router (only needs pool_part)
    router_kernel<<<B_, 256>>>(pool_part, Wp, bp, probs_out, chosen_out);

    // 3) weight transpose+convert (both tensors, one launch)
    wtrans_kernel<<<dim3(H_ / 32, H_ / 32, E_ * 2), 256>>>(W1, W2, w1t, w2t);

    // 4) h = relu(x @ W1[e] + b1[e])  : M=512, N=2048, K=512
    moe_gemm_kernel<true><<<dim3(H_ / 128, T_ / 128, B_), 256, GEMM_SMEM>>>(
        xh, w1t, b1, nullptr, hh, D_, H_);

    // 5) final = h @ W2[e] + b2[e]    : M=512, N=512, K=2048
    moe_gemm_kernel<false><<<dim3(D_ / 128, T_ / 128, B_), 256, GEMM_SMEM>>>(
        hh, w2t, b2, out, nullptr, H_, D_);
}